// round 10
// baseline (speedup 1.0000x reference)
#include <cuda_runtime.h>
#include <cuda_bf16.h>

#define NN 8192
#define EE 128
#define DD 64
#define KK 32
#define MM 4

// Scratch (device globals — no dynamic allocation allowed)
__device__ float g_Psrc[MM * NN * DD];            // 8 MB: src @ V  per metapath
__device__ float g_Poth[MM * NN * DD];            // 8 MB: other @ W_p per metapath
__device__ float g_H[(size_t)MM * NN * EE];       // 16 MB: H[m][n][e]
__device__ float g_partial[MM * 128];             // per-block sem partial sums
__device__ float g_beta[MM];

__device__ __forceinline__ float tanha(float x) {
    float y;
    asm("tanh.approx.f32 %0, %1;" : "=f"(y) : "f"(x));
    return y;
}

// ---------------------------------------------------------------------------
// K1: dense projections. which==0: g_Psrc[m] = src @ V[m]; which==1: g_Poth[m] = oth @ Wp[m]
// grid (128, M, 2), block 256. Each warp: 8 rows, lane covers d-pair (2*lane, 2*lane+1).
// ---------------------------------------------------------------------------
__global__ __launch_bounds__(256) void proj_kernel(
    const float* __restrict__ src, const float* __restrict__ oth,
    const float* __restrict__ V, const float* __restrict__ Wp)
{
    __shared__ float wsm[EE * DD];  // 32 KB
    const int m = blockIdx.y, which = blockIdx.z;
    const float* A  = which ? oth : src;
    const float* Wg = (which ? Wp : V) + m * EE * DD;
    float* P = (which ? g_Poth : g_Psrc) + (size_t)m * NN * DD;

    const float4* w4 = (const float4*)Wg;
    float4* ws4 = (float4*)wsm;
    for (int i = threadIdx.x; i < EE * DD / 4; i += 256) ws4[i] = w4[i];
    __syncthreads();

    const int warp = threadIdx.x >> 5, lane = threadIdx.x & 31;
    const int row0 = blockIdx.x * 64 + warp * 8;
    const int d2 = lane * 2;

    float2 acc[8];
#pragma unroll
    for (int r = 0; r < 8; r++) { acc[r].x = 0.f; acc[r].y = 0.f; }

    for (int eg = 0; eg < EE; eg += 4) {
        float4 s4[8];
#pragma unroll
        for (int r = 0; r < 8; r++)
            s4[r] = ((const float4*)(A + (size_t)(row0 + r) * EE))[eg >> 2];
#pragma unroll
        for (int j = 0; j < 4; j++) {
            float2 w2 = *(const float2*)&wsm[(eg + j) * DD + d2];
#pragma unroll
            for (int r = 0; r < 8; r++) {
                float sv = (j == 0) ? s4[r].x : (j == 1) ? s4[r].y : (j == 2) ? s4[r].z : s4[r].w;
                acc[r].x = fmaf(sv, w2.x, acc[r].x);
                acc[r].y = fmaf(sv, w2.y, acc[r].y);
            }
        }
    }
#pragma unroll
    for (int r = 0; r < 8; r++)
        *(float2*)&P[(size_t)(row0 + r) * DD + d2] = acc[r];
}

// ---------------------------------------------------------------------------
// K2: attention scores + softmax-with-baseline + H aggregation.
// grid (N/8, M), block 256 (8 warps). One warp per (m, n).
// ---------------------------------------------------------------------------
__global__ __launch_bounds__(256) void attn_kernel(
    const float* __restrict__ src, const float* __restrict__ oth,
    const int* __restrict__ nbrs, const float* __restrict__ Bp,
    const float* __restrict__ X)
{
    const int m = blockIdx.y;
    const int warp = threadIdx.x >> 5, lane = threadIdx.x & 31;
    const int n = blockIdx.x * 8 + warp;

    __shared__ float xs[DD], bs[DD];
    if (threadIdx.x < DD) {
        xs[threadIdx.x] = X[m * DD + threadIdx.x];
        bs[threadIdx.x] = Bp[m * DD + threadIdx.x];
    }
    __syncthreads();

    const int d2 = lane * 2;
    float2 ps = *(const float2*)&g_Psrc[((size_t)m * NN + n) * DD + d2];
    float2 psb;
    psb.x = ps.x + bs[d2];
    psb.y = ps.y + bs[d2 + 1];
    float2 x2 = *(const float2*)&xs[d2];

    const int nbr = nbrs[((size_t)m * NN + n) * KK + lane];

    // Pass 1: cooperative score per neighbor k (coalesced 256B P_oth row reads)
    float myscore = 0.f;
#pragma unroll 4
    for (int k = 0; k < KK; k++) {
        int idx = __shfl_sync(0xffffffffu, nbr, k);
        float2 po = *(const float2*)&g_Poth[((size_t)m * NN + idx) * DD + d2];
        float h0 = tanha(po.x + psb.x);
        float h1 = tanha(po.y + psb.y);
        float p = h0 * x2.x + h1 * x2.y;
#pragma unroll
        for (int o = 16; o; o >>= 1) p += __shfl_xor_sync(0xffffffffu, p, o);
        if (lane == k) myscore = p;
    }

    // Softmax over the FULL axis: K real scores + (n_other-K) phantom baselines
    const float baseline = (m == 0) ? -1e-9f : (1.0f / 8192.0f);
    float mx = myscore;
#pragma unroll
    for (int o = 16; o; o >>= 1) mx = fmaxf(mx, __shfl_xor_sync(0xffffffffu, mx, o));
    mx = fmaxf(mx, baseline);
    float ev = expf(myscore - mx);
    float sum = ev;
#pragma unroll
    for (int o = 16; o; o >>= 1) sum += __shfl_xor_sync(0xffffffffu, sum, o);
    float denom = sum + (8192.0f - 32.0f) * expf(baseline - mx);
    float Aw = ev / denom;

    // Pass 2: H[m][n] = src[n] + sum_k A_k * oth[nbr_k]  (coalesced 512B row reads)
    float4 acc = ((const float4*)(src + (size_t)n * EE))[lane];
#pragma unroll 4
    for (int k = 0; k < KK; k++) {
        int idx = __shfl_sync(0xffffffffu, nbr, k);
        float a  = __shfl_sync(0xffffffffu, Aw, k);
        float4 v = ((const float4*)(oth + (size_t)idx * EE))[lane];
        acc.x = fmaf(a, v.x, acc.x);
        acc.y = fmaf(a, v.y, acc.y);
        acc.z = fmaf(a, v.z, acc.z);
        acc.w = fmaf(a, v.w, acc.w);
    }
    ((float4*)(g_H + ((size_t)m * NN + n) * EE))[lane] = acc;
}

// ---------------------------------------------------------------------------
// K3: sem = tanh(H @ Wq + bq); partial[m][block] = sum_n sem . q  (deterministic)
// grid (128, M), block 256: 8 warps x 8 rows = 64 rows per block.
// ---------------------------------------------------------------------------
__global__ __launch_bounds__(256) void sem_kernel(
    const float* __restrict__ Wq, const float* __restrict__ Bq,
    const float* __restrict__ Qv)
{
    __shared__ float wsm[EE * DD];
    __shared__ float bqs[DD], qs[DD];
    __shared__ float bsum[8];
    const int m = blockIdx.y;

    const float4* w4 = (const float4*)(Wq + m * EE * DD);
    float4* ws4 = (float4*)wsm;
    for (int i = threadIdx.x; i < EE * DD / 4; i += 256) ws4[i] = w4[i];
    if (threadIdx.x < DD) {
        bqs[threadIdx.x] = Bq[m * DD + threadIdx.x];
        qs[threadIdx.x]  = Qv[m * DD + threadIdx.x];
    }
    __syncthreads();

    const int warp = threadIdx.x >> 5, lane = threadIdx.x & 31;
    const int d2 = lane * 2;
    float psum = 0.f;

    for (int r = 0; r < 8; r++) {
        const int n = blockIdx.x * 64 + warp * 8 + r;
        const float* Hrow = g_H + ((size_t)m * NN + n) * EE;
        float h0 = Hrow[lane], h1 = Hrow[lane + 32], h2 = Hrow[lane + 64], h3 = Hrow[lane + 96];
        float a0 = 0.f, a1 = 0.f;
#pragma unroll
        for (int e = 0; e < EE; e++) {
            float srcr = (e < 32) ? h0 : (e < 64) ? h1 : (e < 96) ? h2 : h3;
            float hv = __shfl_sync(0xffffffffu, srcr, e & 31);
            float2 w2 = *(const float2*)&wsm[e * DD + d2];
            a0 = fmaf(hv, w2.x, a0);
            a1 = fmaf(hv, w2.y, a1);
        }
        float t0 = tanhf(a0 + bqs[d2]);
        float t1 = tanhf(a1 + bqs[d2 + 1]);
        psum += t0 * qs[d2] + t1 * qs[d2 + 1];
    }
#pragma unroll
    for (int o = 16; o; o >>= 1) psum += __shfl_xor_sync(0xffffffffu, psum, o);
    if (lane == 0) bsum[warp] = psum;
    __syncthreads();
    if (threadIdx.x == 0) {
        float t = 0.f;
        for (int w = 0; w < 8; w++) t += bsum[w];
        g_partial[m * 128 + blockIdx.x] = t;
    }
}

// ---------------------------------------------------------------------------
// K_beta: beta = softmax(mean_n(sem.q)) over metapaths. <<<1,128>>>
// ---------------------------------------------------------------------------
__global__ void beta_kernel()
{
    __shared__ float raw[MM];
    const int m = threadIdx.x >> 5, lane = threadIdx.x & 31;
    float v = g_partial[m * 128 + lane] + g_partial[m * 128 + 32 + lane]
            + g_partial[m * 128 + 64 + lane] + g_partial[m * 128 + 96 + lane];
#pragma unroll
    for (int o = 16; o; o >>= 1) v += __shfl_xor_sync(0xffffffffu, v, o);
    if (lane == 0) raw[m] = v * (1.0f / 8192.0f);
    __syncthreads();
    if (threadIdx.x == 0) {
        float mx = raw[0];
        for (int i = 1; i < MM; i++) mx = fmaxf(mx, raw[i]);
        float e[MM], s = 0.f;
        for (int i = 0; i < MM; i++) { e[i] = expf(raw[i] - mx); s += e[i]; }
        for (int i = 0; i < MM; i++) g_beta[i] = e[i] / s;
    }
}

// ---------------------------------------------------------------------------
// K4: out[n][e] = sum_m beta[m] * H[m][n][e].  grid 1024, block 256 (float4).
// ---------------------------------------------------------------------------
__global__ __launch_bounds__(256) void combine_kernel(float* __restrict__ out)
{
    __shared__ float b[MM];
    if (threadIdx.x < MM) b[threadIdx.x] = g_beta[threadIdx.x];
    __syncthreads();
    const size_t i = (size_t)blockIdx.x * 256 + threadIdx.x;  // float4 index
    const float4* H4 = (const float4*)g_H;
    const size_t stride = (size_t)NN * EE / 4;
    float4 r = H4[i];
    r.x *= b[0]; r.y *= b[0]; r.z *= b[0]; r.w *= b[0];
#pragma unroll
    for (int m = 1; m < MM; m++) {
        float4 v = H4[(size_t)m * stride + i];
        r.x = fmaf(b[m], v.x, r.x);
        r.y = fmaf(b[m], v.y, r.y);
        r.z = fmaf(b[m], v.z, r.z);
        r.w = fmaf(b[m], v.w, r.w);
    }
    ((float4*)out)[i] = r;
}

// ---------------------------------------------------------------------------
// Launcher: two phases; phase 1's "other" is the freshly written user_out in d_out.
// ---------------------------------------------------------------------------
extern "C" void kernel_launch(void* const* d_in, const int* in_sizes, int n_in,
                              void* d_out, int out_size)
{
    const float* user    = (const float*)d_in[0];
    const float* product = (const float*)d_in[1];
    const float* V       = (const float*)d_in[2];
    const float* X       = (const float*)d_in[3];
    const float* Wp      = (const float*)d_in[4];
    const float* Bp      = (const float*)d_in[5];
    const float* Wq      = (const float*)d_in[6];
    const float* Bq      = (const float*)d_in[7];
    const float* Q       = (const float*)d_in[8];
    const int*   unb     = (const int*)d_in[9];
    const int*   pnb     = (const int*)d_in[10];
    float* out = (float*)d_out;

    const int MED = MM * EE * DD;  // per-phase stride of V/Wp/Wq
    const int MDc = MM * DD;       // per-phase stride of X/Bp/Bq/Q

    for (int p = 0; p < 2; p++) {
        const float* src = p ? product : user;
        const float* oth = p ? out : product;   // phase 1 attends over updated user_out
        const int*   nb  = p ? pnb : unb;
        float* outp = out + (size_t)p * NN * EE;

        proj_kernel<<<dim3(128, MM, 2), 256>>>(src, oth, V + p * MED, Wp + p * MED);
        attn_kernel<<<dim3(NN / 8, MM), 256>>>(src, oth, nb, Bp + p * MDc, X + p * MDc);
        sem_kernel<<<dim3(128, MM), 256>>>(Wq + p * MED, Bq + p * MDc, Q + p * MDc);
        beta_kernel<<<1, 128>>>();
        combine_kernel<<<1024, 256>>>(outp);
    }
}